// round 1
// baseline (speedup 1.0000x reference)
#include <cuda_runtime.h>
#include <cstdint>

// ---- JAX RNG scheme: 1 = threefry_partitionable (default in JAX >= 0.5), 0 = original
#define JAX_PARTITIONABLE 1

#define BB 16
#define KG 50
#define AA 9
#define HH 64
#define WW 64
#define HWV 4096
#define NN 36864                      // HH*WW*AA
#define LBL_SZ (BB*AA*HWV)            // 589824
#define CH_SZ  (BB*36*HWV)            // 2359296

// ---------------- scratch (static device globals; no runtime allocs) --------
__device__ float g_ovr[BB*KG*NN];     // [b][k][n]  ~118MB
__device__ float g_maxovr[BB*NN];
__device__ unsigned char g_arg[BB*NN];
__device__ unsigned g_gtmax[BB*KG];   // float bit pattern, atomicMax (vals >= 0)
__device__ float g_lbl[BB*NN];
__device__ float g_uw[BB];

// base anchors for base_size=16, ratios (0.5,1,2), scales (8,16,32)
__constant__ float c_anch[9][4] = {
  {-84.f,-40.f,99.f,55.f},
  {-176.f,-88.f,191.f,103.f},
  {-360.f,-184.f,375.f,199.f},
  {-56.f,-56.f,71.f,71.f},
  {-120.f,-120.f,135.f,135.f},
  {-248.f,-248.f,263.f,263.f},
  {-36.f,-80.f,51.f,95.f},
  {-80.f,-168.f,95.f,183.f},
  {-168.f,-344.f,183.f,359.f}
};

// ---------------- threefry-2x32 (20 rounds), matches JAX ---------------------
__host__ __device__ inline void tf2x32(unsigned k0, unsigned k1,
                                       unsigned x0, unsigned x1,
                                       unsigned &o0, unsigned &o1) {
  unsigned ks2 = k0 ^ k1 ^ 0x1BD11BDAu;
#define TF_R(r) { x0 += x1; x1 = (x1<<(r))|(x1>>(32-(r))); x1 ^= x0; }
  x0 += k0; x1 += k1;
  TF_R(13) TF_R(15) TF_R(26) TF_R(6)
  x0 += k1; x1 += ks2 + 1u;
  TF_R(17) TF_R(29) TF_R(16) TF_R(24)
  x0 += ks2; x1 += k0 + 2u;
  TF_R(13) TF_R(15) TF_R(26) TF_R(6)
  x0 += k0; x1 += k1 + 3u;
  TF_R(17) TF_R(29) TF_R(16) TF_R(24)
  x0 += k1; x1 += ks2 + 4u;
  TF_R(13) TF_R(15) TF_R(26) TF_R(6)
  x0 += ks2; x1 += k0 + 5u;
#undef TF_R
  o0 = x0; o1 = x1;
}

// 23-bit uniform mantissa for anchor index n (monotone with jax uniform value)
__device__ inline unsigned rng23(unsigned k0, unsigned k1, unsigned n) {
#if JAX_PARTITIONABLE
  unsigned o0, o1; tf2x32(k0, k1, 0u, n, o0, o1);
  return (o0 ^ o1) >> 9;
#else
  const unsigned half = NN/2;
  unsigned o0, o1;
  if (n < half) { tf2x32(k0, k1, n, n + half, o0, o1); return o0 >> 9; }
  tf2x32(k0, k1, n - half, n, o0, o1); return o1 >> 9;
#endif
}

// ---------------- kernels ----------------------------------------------------
__global__ void zero_gtmax_kernel() {
  int i = threadIdx.x;
  if (i < BB*KG) g_gtmax[i] = 0u;
}

__global__ void iou_kernel(const float* __restrict__ gt,
                           const float* __restrict__ iminfo) {
  int b = blockIdx.y;
  int n = blockIdx.x * 256 + threadIdx.x;
  int t = threadIdx.x;
  __shared__ float sg[KG][5];
  __shared__ unsigned smax[KG];
  if (t < KG) {
    const float* g = gt + (b*KG + t)*5;
    float x1 = g[0], y1 = g[1], x2 = g[2], y2 = g[3];
    sg[t][0] = x1; sg[t][1] = y1; sg[t][2] = x2; sg[t][3] = y2;
    sg[t][4] = (x2 - x1 + 1.f) * (y2 - y1 + 1.f);
    smax[t] = 0u;
  }
  __syncthreads();
  float imh = iminfo[0], imw = iminfo[1];
  int a = n % AA; int s = n / AA;
  float fx = (float)((s & 63) * 16);
  float fy = (float)((s >> 6) * 16);
  float ax1 = c_anch[a][0] + fx, ay1 = c_anch[a][1] + fy;
  float ax2 = c_anch[a][2] + fx, ay2 = c_anch[a][3] + fy;
  bool inside = (ax1 >= 0.f) && (ay1 >= 0.f) && (ax2 < imw) && (ay2 < imh);
  float aw = ax2 - ax1 + 1.f, ah = ay2 - ay1 + 1.f;
  float aarea = aw * ah;
  float best = -1.f; int arg = 0;
#pragma unroll 5
  for (int k = 0; k < KG; k++) {
    float ix = fmaxf(0.f, fminf(ax2, sg[k][2]) - fmaxf(ax1, sg[k][0]) + 1.f);
    float iy = fmaxf(0.f, fminf(ay2, sg[k][3]) - fmaxf(ay1, sg[k][1]) + 1.f);
    float inter = ix * iy;
    float ovr = inter / (aarea + sg[k][4] - inter);
    g_ovr[(b*KG + k)*NN + n] = ovr;
    if (ovr > best) { best = ovr; arg = k; }
    unsigned v = inside ? __float_as_uint(ovr) : 0u;
    unsigned m = __reduce_max_sync(0xffffffffu, v);
    if ((t & 31) == 0 && m) atomicMax(&smax[k], m);
  }
  g_maxovr[b*NN + n] = best;
  g_arg[b*NN + n] = (unsigned char)arg;
  __syncthreads();
  if (t < KG) atomicMax(&g_gtmax[b*KG + t], smax[t]);
}

__global__ void labels_kernel(const float* __restrict__ iminfo) {
  int b = blockIdx.y;
  int n = blockIdx.x * 256 + threadIdx.x;
  __shared__ float sgm[KG];
  if (threadIdx.x < KG) {
    float f = __uint_as_float(g_gtmax[b*KG + threadIdx.x]);
    sgm[threadIdx.x] = (f == 0.f) ? 1e-5f : f;
  }
  __syncthreads();
  float imh = iminfo[0], imw = iminfo[1];
  int a = n % AA; int s = n / AA;
  float fx = (float)((s & 63) * 16);
  float fy = (float)((s >> 6) * 16);
  float ax1 = c_anch[a][0] + fx, ay1 = c_anch[a][1] + fy;
  float ax2 = c_anch[a][2] + fx, ay2 = c_anch[a][3] + fy;
  bool inside = (ax1 >= 0.f) && (ay1 >= 0.f) && (ax2 < imw) && (ay2 < imh);
  float lbl = -1.f;
  if (inside) {
    float mo = g_maxovr[b*NN + n];
    bool isb = false;
#pragma unroll 5
    for (int k = 0; k < KG; k++)
      isb |= (g_ovr[(b*KG + k)*NN + n] == sgm[k]);
    if (mo < 0.3f) lbl = 0.f;
    if (isb)       lbl = 1.f;
    if (mo >= 0.7f) lbl = 1.f;
  }
  g_lbl[b*NN + n] = lbl;
}

struct Keys { unsigned k[BB][4]; };  // kf0,kf1,kb0,kb1 per batch

// keep top `limit` masked entries by (23-bit value desc, index asc); disable rest
__device__ void do_select(float* lbl, float maskval, int limit,
                          unsigned k0, unsigned k1,
                          int* hist, unsigned* lv, int* li, int* sc,
                          int t, int nt) {
  for (int i = t; i < 4096; i += nt) hist[i] = 0;
  if (t == 0) sc[0] = 0;
  __syncthreads();
  for (int n = t; n < NN; n += nt) {
    if (lbl[n] == maskval) {
      unsigned v = rng23(k0, k1, (unsigned)n);
      atomicAdd(&hist[v >> 11], 1);
    }
  }
  __syncthreads();
  if (t == 0) {
    int cum = 0, cb = 0, r = limit;
    for (int bkt = 4095; bkt >= 0; bkt--) {
      int h = hist[bkt];
      if (cum + h >= limit) { cb = bkt; r = limit - cum; break; }
      cum += h;
    }
    sc[1] = cb; sc[2] = r;
  }
  __syncthreads();
  int cb = sc[1], r = sc[2];
  for (int n = t; n < NN; n += nt) {
    if (lbl[n] == maskval) {
      unsigned v = rng23(k0, k1, (unsigned)n);
      int bkt = (int)(v >> 11);
      if (bkt < cb) lbl[n] = -1.f;
      else if (bkt == cb) {
        int p = atomicAdd(&sc[0], 1);
        if (p < 2048) { lv[p] = v; li[p] = n; }
        else lbl[n] = -1.f;   // statistically unreachable overflow guard
      }
    }
  }
  __syncthreads();
  int m = min(sc[0], 2048);
  for (int i = t; i < m; i += nt) {
    unsigned vi = lv[i]; int ni = li[i]; int rank = 0;
    for (int j = 0; j < m; j++) {
      unsigned vj = lv[j];
      if (vj > vi || (vj == vi && li[j] < ni)) rank++;
    }
    if (rank >= r) lbl[ni] = -1.f;
  }
  __syncthreads();
}

__global__ void subsample_kernel(Keys keys) {
  int b = blockIdx.x; int t = threadIdx.x; int nt = blockDim.x;
  __shared__ int hist[4096];
  __shared__ unsigned lv[2048];
  __shared__ int li[2048];
  __shared__ int sc[4];
  float* lbl = g_lbl + b*NN;
  if (t == 0) sc[3] = 0;
  __syncthreads();
  int c = 0;
  for (int n = t; n < NN; n += nt) c += (lbl[n] == 1.f);
  atomicAdd(&sc[3], c);
  __syncthreads();
  int fgc = sc[3];
  int fg_kept = min(fgc, 128);
  if (fgc > 128)
    do_select(lbl, 1.f, 128, keys.k[b][0], keys.k[b][1], hist, lv, li, sc, t, nt);
  __syncthreads();
  if (t == 0) sc[3] = 0;
  __syncthreads();
  c = 0;
  for (int n = t; n < NN; n += nt) c += (lbl[n] == 0.f);
  atomicAdd(&sc[3], c);
  __syncthreads();
  int bgc = sc[3];
  int limit = 256 - fg_kept;
  if (bgc > limit)
    do_select(lbl, 0.f, limit, keys.k[b][2], keys.k[b][3], hist, lv, li, sc, t, nt);
  int kept = fg_kept + min(bgc, limit);
  if (t == 0) g_uw[b] = 1.f / (float)kept;
}

__global__ void output_kernel(const float* __restrict__ gt,
                              const float* __restrict__ iminfo,
                              float* __restrict__ out) {
  int idx = blockIdx.x * 256 + threadIdx.x;      // exactly LBL_SZ threads
  int s = idx & (HWV - 1);
  int t12 = idx >> 12;
  int a = t12 % AA;
  int b = t12 / AA;
  int n = s * AA + a;
  float fx = (float)((s & 63) * 16);
  float fy = (float)((s >> 6) * 16);
  float ax1 = c_anch[a][0] + fx, ay1 = c_anch[a][1] + fy;
  float ax2 = c_anch[a][2] + fx, ay2 = c_anch[a][3] + fy;
  float imh = iminfo[0], imw = iminfo[1];
  bool inside = (ax1 >= 0.f) && (ay1 >= 0.f) && (ax2 < imw) && (ay2 < imh);
  float lbl = g_lbl[b*NN + n];
  int arg = (int)g_arg[b*NN + n];
  const float* g = gt + (b*KG + arg)*5;
  float aw = ax2 - ax1 + 1.f, ah = ay2 - ay1 + 1.f;
  float acx = ax1 + 0.5f*(aw - 1.f), acy = ay1 + 0.5f*(ah - 1.f);
  float gw = g[2] - g[0] + 1.f, gh = g[3] - g[1] + 1.f;
  float gcx = g[0] + 0.5f*(gw - 1.f), gcy = g[1] + 0.5f*(gh - 1.f);
  float t0 = (gcx - acx) / aw;
  float t1 = (gcy - acy) / ah;
  float t2 = logf(gw / aw);
  float t3 = logf(gh / ah);
  float inw = (lbl == 1.f) ? 1.f : 0.f;
  float ow  = (lbl == 1.f || lbl == 0.f) ? g_uw[b] : 0.f;
  if (!inside) { t0 = t1 = t2 = t3 = 0.f; inw = 0.f; ow = 0.f; lbl = 0.f; }
  out[idx] = lbl;                               // labels: b*9*4096 + a*4096 + s
  int cb = (b*36 + a*4)*HWV + s;
  float tv[4] = {t0, t1, t2, t3};
#pragma unroll
  for (int c4 = 0; c4 < 4; c4++) {
    out[LBL_SZ            + cb + c4*HWV] = tv[c4];
    out[LBL_SZ +   CH_SZ  + cb + c4*HWV] = inw;
    out[LBL_SZ + 2*CH_SZ  + cb + c4*HWV] = ow;
  }
}

// ---------------- host --------------------------------------------------------
extern "C" void kernel_launch(void* const* d_in, const int* in_sizes, int n_in,
                              void* d_out, int out_size) {
  const float* gt     = (const float*)d_in[1];   // (B,50,5)
  const float* iminfo = (const float*)d_in[2];   // (B,2), ref uses row 0
  float* out = (float*)d_out;

  Keys keys;
  for (int b = 0; b < BB; b++) {
#if JAX_PARTITIONABLE
    unsigned b0, b1; tf2x32(0u, 42u, 0u, (unsigned)b, b0, b1);
    unsigned f0, f1, g0, g1;
    tf2x32(b0, b1, 0u, 0u, f0, f1);
    tf2x32(b0, b1, 0u, 1u, g0, g1);
    keys.k[b][0] = f0; keys.k[b][1] = f1; keys.k[b][2] = g0; keys.k[b][3] = g1;
#else
    // split(root,16): pairs (i, i+16); out=concat(y0,y1); key_b = (flat[2b], flat[2b+1])
    unsigned y0[16], y1[16], flat[32];
    for (int i = 0; i < 16; i++) tf2x32(0u, 42u, (unsigned)i, (unsigned)(i+16), y0[i], y1[i]);
    for (int i = 0; i < 16; i++) { flat[i] = y0[i]; flat[16+i] = y1[i]; }
    unsigned kb0 = flat[2*b], kb1 = flat[2*b+1];
    unsigned p00, p01, p10, p11;
    tf2x32(kb0, kb1, 0u, 2u, p00, p01);
    tf2x32(kb0, kb1, 1u, 3u, p10, p11);
    keys.k[b][0] = p00; keys.k[b][1] = p10;   // kf
    keys.k[b][2] = p01; keys.k[b][3] = p11;   // kb
#endif
  }

  zero_gtmax_kernel<<<1, 800>>>();
  dim3 gA(NN/256, BB);
  iou_kernel<<<gA, 256>>>(gt, iminfo);
  labels_kernel<<<gA, 256>>>(iminfo);
  subsample_kernel<<<BB, 512>>>(keys);
  output_kernel<<<LBL_SZ/256, 256>>>(gt, iminfo, out);
}

// round 2
// speedup vs baseline: 1.4339x; 1.4339x over previous
#include <cuda_runtime.h>
#include <cstdint>

#define JAX_PARTITIONABLE 1

#define BB 16
#define KG 50
#define AA 9
#define HWV 4096
#define NN 36864                      // 64*64*9
#define LBL_SZ (BB*AA*HWV)            // 589824
#define CH_SZ  (BB*36*HWV)            // 2359296
#define NT 1024                       // subsample block size

// ---------------- scratch -----------------------------------------------------
__device__ unsigned g_gtmax[BB*KG];   // float bit pattern, atomicMax (vals >= 0)
__device__ float g_lbl[BB*NN];
__device__ unsigned char g_arg[BB*NN];
__device__ float g_uw[BB];
__device__ int g_fgl[BB*NN];
__device__ int g_bgl[BB*NN];

__constant__ float c_anch[9][4] = {
  {-84.f,-40.f,99.f,55.f},
  {-176.f,-88.f,191.f,103.f},
  {-360.f,-184.f,375.f,199.f},
  {-56.f,-56.f,71.f,71.f},
  {-120.f,-120.f,135.f,135.f},
  {-248.f,-248.f,263.f,263.f},
  {-36.f,-80.f,51.f,95.f},
  {-80.f,-168.f,95.f,183.f},
  {-168.f,-344.f,183.f,359.f}
};

// ---------------- threefry-2x32 (20 rounds), matches JAX ----------------------
__host__ __device__ inline void tf2x32(unsigned k0, unsigned k1,
                                       unsigned x0, unsigned x1,
                                       unsigned &o0, unsigned &o1) {
  unsigned ks2 = k0 ^ k1 ^ 0x1BD11BDAu;
#define TF_R(r) { x0 += x1; x1 = (x1<<(r))|(x1>>(32-(r))); x1 ^= x0; }
  x0 += k0; x1 += k1;
  TF_R(13) TF_R(15) TF_R(26) TF_R(6)
  x0 += k1; x1 += ks2 + 1u;
  TF_R(17) TF_R(29) TF_R(16) TF_R(24)
  x0 += ks2; x1 += k0 + 2u;
  TF_R(13) TF_R(15) TF_R(26) TF_R(6)
  x0 += k0; x1 += k1 + 3u;
  TF_R(17) TF_R(29) TF_R(16) TF_R(24)
  x0 += k1; x1 += ks2 + 4u;
  TF_R(13) TF_R(15) TF_R(26) TF_R(6)
  x0 += ks2; x1 += k0 + 5u;
#undef TF_R
  o0 = x0; o1 = x1;
}

__device__ inline unsigned rng23(unsigned k0, unsigned k1, unsigned n) {
#if JAX_PARTITIONABLE
  unsigned o0, o1; tf2x32(k0, k1, 0u, n, o0, o1);
  return (o0 ^ o1) >> 9;
#else
  const unsigned half = NN/2;
  unsigned o0, o1;
  if (n < half) { tf2x32(k0, k1, n, n + half, o0, o1); return o0 >> 9; }
  tf2x32(k0, k1, n - half, n, o0, o1); return o1 >> 9;
#endif
}

// ---------------- bit-deterministic IoU helper --------------------------------
// All FP ops via _rn intrinsics so stats_kernel and labels_kernel produce
// identical bit patterns (required for the ovr == gt_max equality check).
__device__ __forceinline__ float iou_rn(float ax1, float ay1, float ax2, float ay2,
                                        float aarea,
                                        float gx1, float gy1, float gx2, float gy2,
                                        float garea) {
  float ix = fmaxf(0.f, __fadd_rn(__fsub_rn(fminf(ax2, gx2), fmaxf(ax1, gx1)), 1.f));
  float iy = fmaxf(0.f, __fadd_rn(__fsub_rn(fminf(ay2, gy2), fmaxf(ay1, gy1)), 1.f));
  float inter = __fmul_rn(ix, iy);
  float den = __fsub_rn(__fadd_rn(aarea, garea), inter);
  return __fdiv_rn(inter, den);
}

struct Anchor { float x1, y1, x2, y2, area; bool inside; };

__device__ __forceinline__ Anchor mk_anchor(int n, float imw, float imh) {
  Anchor A;
  int a = n % AA; int s = n / AA;
  float fx = (float)((s & 63) * 16);
  float fy = (float)((s >> 6) * 16);
  A.x1 = __fadd_rn(c_anch[a][0], fx); A.y1 = __fadd_rn(c_anch[a][1], fy);
  A.x2 = __fadd_rn(c_anch[a][2], fx); A.y2 = __fadd_rn(c_anch[a][3], fy);
  float aw = __fadd_rn(__fsub_rn(A.x2, A.x1), 1.f);
  float ah = __fadd_rn(__fsub_rn(A.y2, A.y1), 1.f);
  A.area = __fmul_rn(aw, ah);
  A.inside = (A.x1 >= 0.f) && (A.y1 >= 0.f) && (A.x2 < imw) && (A.y2 < imh);
  return A;
}

// ---------------- kernels -----------------------------------------------------
__global__ void zero_gtmax_kernel() {
  int i = threadIdx.x;
  if (i < BB*KG) g_gtmax[i] = 0u;
}

// per-GT max IoU over inside anchors
__global__ void stats_kernel(const float* __restrict__ gt,
                             const float* __restrict__ iminfo) {
  int b = blockIdx.y;
  int n = blockIdx.x * 256 + threadIdx.x;
  int t = threadIdx.x;
  __shared__ float sg[KG][5];
  __shared__ unsigned smax[KG];
  if (t < KG) {
    const float* g = gt + (b*KG + t)*5;
    float x1 = g[0], y1 = g[1], x2 = g[2], y2 = g[3];
    sg[t][0] = x1; sg[t][1] = y1; sg[t][2] = x2; sg[t][3] = y2;
    sg[t][4] = __fmul_rn(__fadd_rn(__fsub_rn(x2, x1), 1.f),
                         __fadd_rn(__fsub_rn(y2, y1), 1.f));
    smax[t] = 0u;
  }
  __syncthreads();
  float imh = iminfo[0], imw = iminfo[1];
  Anchor A = mk_anchor(n, imw, imh);
#pragma unroll 5
  for (int k = 0; k < KG; k++) {
    float ovr = iou_rn(A.x1, A.y1, A.x2, A.y2, A.area,
                       sg[k][0], sg[k][1], sg[k][2], sg[k][3], sg[k][4]);
    unsigned v = A.inside ? __float_as_uint(ovr) : 0u;
    unsigned m = __reduce_max_sync(0xffffffffu, v);
    if ((t & 31) == 0 && m) atomicMax(&smax[k], m);
  }
  __syncthreads();
  if (t < KG && smax[t]) atomicMax(&g_gtmax[b*KG + t], smax[t]);
}

// recompute IoUs (bit-identical), produce labels + argmax
__global__ void labels_kernel(const float* __restrict__ gt,
                              const float* __restrict__ iminfo) {
  int b = blockIdx.y;
  int n = blockIdx.x * 256 + threadIdx.x;
  int t = threadIdx.x;
  __shared__ float sg[KG][5];
  __shared__ float sgm[KG];
  if (t < KG) {
    const float* g = gt + (b*KG + t)*5;
    float x1 = g[0], y1 = g[1], x2 = g[2], y2 = g[3];
    sg[t][0] = x1; sg[t][1] = y1; sg[t][2] = x2; sg[t][3] = y2;
    sg[t][4] = __fmul_rn(__fadd_rn(__fsub_rn(x2, x1), 1.f),
                         __fadd_rn(__fsub_rn(y2, y1), 1.f));
    float f = __uint_as_float(g_gtmax[b*KG + t]);
    sgm[t] = (f == 0.f) ? 1e-5f : f;
  }
  __syncthreads();
  float imh = iminfo[0], imw = iminfo[1];
  Anchor A = mk_anchor(n, imw, imh);
  float best = -1.f; int arg = 0; bool isb = false;
#pragma unroll 5
  for (int k = 0; k < KG; k++) {
    float ovr = iou_rn(A.x1, A.y1, A.x2, A.y2, A.area,
                       sg[k][0], sg[k][1], sg[k][2], sg[k][3], sg[k][4]);
    if (ovr > best) { best = ovr; arg = k; }
    isb |= (ovr == sgm[k]);
  }
  float lbl = -1.f;
  if (A.inside) {
    if (best < 0.3f) lbl = 0.f;
    if (isb)         lbl = 1.f;
    if (best >= 0.7f) lbl = 1.f;
  }
  g_lbl[b*NN + n] = lbl;
  g_arg[b*NN + n] = (unsigned char)arg;
}

struct Keys { unsigned k[BB][4]; };

// keep top `limit` candidates by (23-bit rng desc, index asc); disable rest
__device__ void select_top(float* __restrict__ lbl, const int* __restrict__ list,
                           int cnt, int limit, unsigned k0, unsigned k1,
                           int* hist, unsigned* tie_v, int* tie_n,
                           int* wsum, int* s_sel, int t) {
#pragma unroll
  for (int i = t; i < 4096; i += NT) hist[i] = 0;
  if (t == 0) s_sel[2] = 0;
  __syncthreads();
  for (int i = t; i < cnt; i += NT) {
    unsigned v = rng23(k0, k1, (unsigned)list[i]);
    atomicAdd(&hist[v >> 11], 1);
  }
  __syncthreads();
  // parallel suffix scan: thread t owns descending bucket chunk [4095-4t .. 4092-4t]
  int base = 4095 - 4*t;
  int h0 = hist[base], h1 = hist[base-1], h2 = hist[base-2], h3 = hist[base-3];
  int local = h0 + h1 + h2 + h3;
  int lane = t & 31, wid = t >> 5;
  int x = local;
#pragma unroll
  for (int o = 1; o < 32; o <<= 1) {
    int y = __shfl_up_sync(0xffffffffu, x, o);
    if (lane >= o) x += y;
  }
  if (lane == 31) wsum[wid] = x;
  __syncthreads();
  if (wid == 0) {
    int s = wsum[lane];
#pragma unroll
    for (int o = 1; o < 32; o <<= 1) {
      int y = __shfl_up_sync(0xffffffffu, s, o);
      if (lane >= o) s += y;
    }
    wsum[lane] = s;
  }
  __syncthreads();
  int prefix = (wid ? wsum[wid-1] : 0) + (x - local);   // count strictly above chunk
  if (prefix < limit && prefix + local >= limit) {
    int p = prefix; int hh[4] = {h0, h1, h2, h3};
#pragma unroll
    for (int j = 0; j < 4; j++) {
      if (p + hh[j] >= limit) { s_sel[0] = base - j; s_sel[1] = limit - p; break; }
      p += hh[j];
    }
  }
  __syncthreads();
  int cb = s_sel[0], r = s_sel[1];
  for (int i = t; i < cnt; i += NT) {
    int n = list[i];
    unsigned v = rng23(k0, k1, (unsigned)n);
    int bkt = (int)(v >> 11);
    if (bkt < cb) lbl[n] = -1.f;
    else if (bkt == cb) {
      int p = atomicAdd(&s_sel[2], 1);
      if (p < 1024) { tie_v[p] = v; tie_n[p] = n; }
      else lbl[n] = -1.f;   // statistically unreachable overflow guard
    }
  }
  __syncthreads();
  int m = min(s_sel[2], 1024);
  for (int i = t; i < m; i += NT) {
    unsigned vi = tie_v[i]; int ni = tie_n[i]; int rank = 0;
    for (int j = 0; j < m; j++) {
      unsigned vj = tie_v[j];
      if (vj > vi || (vj == vi && tie_n[j] < ni)) rank++;
    }
    if (rank >= r) lbl[ni] = -1.f;
  }
  __syncthreads();
}

__global__ __launch_bounds__(NT) void subsample_kernel(Keys keys) {
  int b = blockIdx.x; int t = threadIdx.x;
  __shared__ int hist[4096];
  __shared__ unsigned tie_v[1024];
  __shared__ int tie_n[1024];
  __shared__ int wsum[32];
  __shared__ int s_cnt[2];
  __shared__ int s_sel[3];
  float* lbl = g_lbl + b*NN;
  int* fgl = g_fgl + b*NN;
  int* bgl = g_bgl + b*NN;
  if (t < 2) s_cnt[t] = 0;
  __syncthreads();
  for (int n = t; n < NN; n += NT) {
    float l = lbl[n];
    if (l == 1.f)      { int p = atomicAdd(&s_cnt[0], 1); fgl[p] = n; }
    else if (l == 0.f) { int p = atomicAdd(&s_cnt[1], 1); bgl[p] = n; }
  }
  __syncthreads();
  int fgc = s_cnt[0], bgc = s_cnt[1];
  if (fgc > 128)
    select_top(lbl, fgl, fgc, 128, keys.k[b][0], keys.k[b][1],
               hist, tie_v, tie_n, wsum, s_sel, t);
  int fg_kept = min(fgc, 128);
  int limit = 256 - fg_kept;
  if (bgc > limit)
    select_top(lbl, bgl, bgc, limit, keys.k[b][2], keys.k[b][3],
               hist, tie_v, tie_n, wsum, s_sel, t);
  int kept = fg_kept + min(bgc, limit);
  if (t == 0) g_uw[b] = 1.f / (float)kept;
}

__global__ void output_kernel(const float* __restrict__ gt,
                              const float* __restrict__ iminfo,
                              float* __restrict__ out) {
  int idx = blockIdx.x * 256 + threadIdx.x;      // exactly LBL_SZ threads
  int s = idx & (HWV - 1);
  int t12 = idx >> 12;
  int a = t12 % AA;
  int b = t12 / AA;
  int n = s * AA + a;
  float imh = iminfo[0], imw = iminfo[1];
  float fx = (float)((s & 63) * 16);
  float fy = (float)((s >> 6) * 16);
  float ax1 = c_anch[a][0] + fx, ay1 = c_anch[a][1] + fy;
  float ax2 = c_anch[a][2] + fx, ay2 = c_anch[a][3] + fy;
  bool inside = (ax1 >= 0.f) && (ay1 >= 0.f) && (ax2 < imw) && (ay2 < imh);
  float lbl = g_lbl[b*NN + n];
  int arg = (int)g_arg[b*NN + n];
  const float* g = gt + (b*KG + arg)*5;
  float aw = ax2 - ax1 + 1.f, ah = ay2 - ay1 + 1.f;
  float acx = ax1 + 0.5f*(aw - 1.f), acy = ay1 + 0.5f*(ah - 1.f);
  float gw = g[2] - g[0] + 1.f, gh = g[3] - g[1] + 1.f;
  float gcx = g[0] + 0.5f*(gw - 1.f), gcy = g[1] + 0.5f*(gh - 1.f);
  float t0 = (gcx - acx) / aw;
  float t1 = (gcy - acy) / ah;
  float t2 = logf(gw / aw);
  float t3 = logf(gh / ah);
  float inw = (lbl == 1.f) ? 1.f : 0.f;
  float ow  = (lbl == 1.f || lbl == 0.f) ? g_uw[b] : 0.f;
  if (!inside) { t0 = t1 = t2 = t3 = 0.f; inw = 0.f; ow = 0.f; lbl = 0.f; }
  out[idx] = lbl;
  int cb = (b*36 + a*4)*HWV + s;
  float tv[4] = {t0, t1, t2, t3};
#pragma unroll
  for (int c4 = 0; c4 < 4; c4++) {
    out[LBL_SZ            + cb + c4*HWV] = tv[c4];
    out[LBL_SZ +   CH_SZ  + cb + c4*HWV] = inw;
    out[LBL_SZ + 2*CH_SZ  + cb + c4*HWV] = ow;
  }
}

// ---------------- host --------------------------------------------------------
extern "C" void kernel_launch(void* const* d_in, const int* in_sizes, int n_in,
                              void* d_out, int out_size) {
  const float* gt     = (const float*)d_in[1];   // (B,50,5)
  const float* iminfo = (const float*)d_in[2];   // (B,2), ref uses row 0
  float* out = (float*)d_out;

  Keys keys;
  for (int b = 0; b < BB; b++) {
#if JAX_PARTITIONABLE
    unsigned b0, b1; tf2x32(0u, 42u, 0u, (unsigned)b, b0, b1);
    unsigned f0, f1, g0, g1;
    tf2x32(b0, b1, 0u, 0u, f0, f1);
    tf2x32(b0, b1, 0u, 1u, g0, g1);
    keys.k[b][0] = f0; keys.k[b][1] = f1; keys.k[b][2] = g0; keys.k[b][3] = g1;
#else
    unsigned y0[16], y1[16], flat[32];
    for (int i = 0; i < 16; i++) tf2x32(0u, 42u, (unsigned)i, (unsigned)(i+16), y0[i], y1[i]);
    for (int i = 0; i < 16; i++) { flat[i] = y0[i]; flat[16+i] = y1[i]; }
    unsigned kb0 = flat[2*b], kb1 = flat[2*b+1];
    unsigned p00, p01, p10, p11;
    tf2x32(kb0, kb1, 0u, 2u, p00, p01);
    tf2x32(kb0, kb1, 1u, 3u, p10, p11);
    keys.k[b][0] = p00; keys.k[b][1] = p10;
    keys.k[b][2] = p01; keys.k[b][3] = p11;
#endif
  }

  zero_gtmax_kernel<<<1, 800>>>();
  dim3 gA(NN/256, BB);
  stats_kernel<<<gA, 256>>>(gt, iminfo);
  labels_kernel<<<gA, 256>>>(gt, iminfo);
  subsample_kernel<<<BB, NT>>>(keys);
  output_kernel<<<LBL_SZ/256, 256>>>(gt, iminfo, out);
}

// round 4
// speedup vs baseline: 1.9595x; 1.3666x over previous
#include <cuda_runtime.h>
#include <cstdint>

#define JAX_PARTITIONABLE 1

#define BB 16
#define KG 50
#define AA 9
#define HWV 4096
#define NN 36864                      // 9*4096
#define LBL_SZ (BB*AA*HWV)            // 589824
#define CH_SZ  (BB*36*HWV)            // 2359296
#define NT 1024

// ---------------- scratch -----------------------------------------------------
__device__ unsigned g_gtmax[BB*KG];   // float bit pattern (vals >= 0)
__device__ float g_lbl[BB*NN];        // indexed by m = a*4096 + s
__device__ unsigned char g_arg[BB*NN];
__device__ float g_uw[BB];
__device__ int  g_cnt[BB*2];          // fg/bg candidate counts
__device__ int2 g_cand[BB*2*NN];      // .x = (n_orig<<16)|m, .y = rng23

__constant__ float c_anch[9][4] = {
  {-84.f,-40.f,99.f,55.f},
  {-176.f,-88.f,191.f,103.f},
  {-360.f,-184.f,375.f,199.f},
  {-56.f,-56.f,71.f,71.f},
  {-120.f,-120.f,135.f,135.f},
  {-248.f,-248.f,263.f,263.f},
  {-36.f,-80.f,51.f,95.f},
  {-80.f,-168.f,95.f,183.f},
  {-168.f,-344.f,183.f,359.f}
};

// ---------------- threefry-2x32 (20 rounds), matches JAX ----------------------
__host__ __device__ inline void tf2x32(unsigned k0, unsigned k1,
                                       unsigned x0, unsigned x1,
                                       unsigned &o0, unsigned &o1) {
  unsigned ks2 = k0 ^ k1 ^ 0x1BD11BDAu;
#define TF_R(r) { x0 += x1; x1 = (x1<<(r))|(x1>>(32-(r))); x1 ^= x0; }
  x0 += k0; x1 += k1;
  TF_R(13) TF_R(15) TF_R(26) TF_R(6)
  x0 += k1; x1 += ks2 + 1u;
  TF_R(17) TF_R(29) TF_R(16) TF_R(24)
  x0 += ks2; x1 += k0 + 2u;
  TF_R(13) TF_R(15) TF_R(26) TF_R(6)
  x0 += k0; x1 += k1 + 3u;
  TF_R(17) TF_R(29) TF_R(16) TF_R(24)
  x0 += k1; x1 += ks2 + 4u;
  TF_R(13) TF_R(15) TF_R(26) TF_R(6)
  x0 += ks2; x1 += k0 + 5u;
#undef TF_R
  o0 = x0; o1 = x1;
}

__device__ inline unsigned rng23(unsigned k0, unsigned k1, unsigned n) {
#if JAX_PARTITIONABLE
  unsigned o0, o1; tf2x32(k0, k1, 0u, n, o0, o1);
  return (o0 ^ o1) >> 9;
#else
  const unsigned half = NN/2;
  unsigned o0, o1;
  if (n < half) { tf2x32(k0, k1, n, n + half, o0, o1); return o0 >> 9; }
  tf2x32(k0, k1, n - half, n, o0, o1); return o1 >> 9;
#endif
}

struct Keys { unsigned k[BB][4]; };

// ---------------- kernels -----------------------------------------------------
__global__ void zero_kernel() {
  int i = blockIdx.x * 256 + threadIdx.x;
  if (i < BB*KG) g_gtmax[i] = 0u;
  if (i < BB*2)  g_cnt[i] = 0;
}

// per-GT max of rounded IoU over inside anchors
__global__ __launch_bounds__(256) void stats_kernel(const float* __restrict__ gt,
                                                    const float* __restrict__ iminfo) {
  int b = blockIdx.y, t = threadIdx.x;
  int m0 = (blockIdx.x * 256 + t) * 4;
  __shared__ float4 sbox[KG];
  __shared__ float sarea[KG];
  __shared__ unsigned smax[KG];
  if (t < KG) {
    const float* g = gt + (b*KG + t)*5;
    float x1 = g[0], y1 = g[1], x2 = g[2], y2 = g[3];
    sbox[t] = make_float4(x1, y1, x2, y2);
    sarea[t] = __fmul_rn(__fadd_rn(__fsub_rn(x2, x1), 1.f),
                         __fadd_rn(__fsub_rn(y2, y1), 1.f));
    smax[t] = 0u;
  }
  __syncthreads();
  float imh = iminfo[0], imw = iminfo[1];
  int a = m0 >> 12;
  int s0 = m0 & 4095;
  float c0 = c_anch[a][0], c1 = c_anch[a][1], c2 = c_anch[a][2], c3 = c_anch[a][3];
  float ax1[4], ay1[4], ax2[4], ay2[4], aarea[4];
  bool ins[4]; bool any = false;
#pragma unroll
  for (int j = 0; j < 4; j++) {
    int s = s0 + j;
    float fx = (float)((s & 63) * 16);
    float fy = (float)((s >> 6) * 16);
    ax1[j] = __fadd_rn(c0, fx); ay1[j] = __fadd_rn(c1, fy);
    ax2[j] = __fadd_rn(c2, fx); ay2[j] = __fadd_rn(c3, fy);
    aarea[j] = __fmul_rn(__fadd_rn(__fsub_rn(ax2[j], ax1[j]), 1.f),
                         __fadd_rn(__fsub_rn(ay2[j], ay1[j]), 1.f));
    ins[j] = (ax1[j] >= 0.f) && (ay1[j] >= 0.f) && (ax2[j] < imw) && (ay2[j] < imh);
    any |= ins[j];
  }
  if (__ballot_sync(0xffffffffu, any)) {
    int wrow = ((m0 & ~127) & 4095) >> 6;          // warp covers rows wrow, wrow+1
    float wy1 = c1 + (float)(wrow * 16);
    float wy2 = c3 + (float)((wrow + 1) * 16);
    for (int k = 0; k < KG; k++) {
      float4 gb = sbox[k];
      // +1-inclusive IoU extent: nonzero iy possible while gb.y < ay2+1 etc.
      if (gb.y - wy2 >= 1.f || wy1 - gb.w >= 1.f) continue;
      float ga = sarea[k];
      float bi = 0.f, bd = 1.f;
#pragma unroll
      for (int j = 0; j < 4; j++) {
        if (!ins[j]) continue;
        float ix = fmaxf(0.f, __fadd_rn(__fsub_rn(fminf(ax2[j], gb.z), fmaxf(ax1[j], gb.x)), 1.f));
        float iy = fmaxf(0.f, __fadd_rn(__fsub_rn(fminf(ay2[j], gb.w), fmaxf(ay1[j], gb.y)), 1.f));
        float inter = __fmul_rn(ix, iy);
        if (inter <= 0.f) continue;
        float den = __fsub_rn(__fadd_rn(aarea[j], ga), inter);
        float L = __fmul_rn(inter, bd), R = __fmul_rn(bi, den);
        if (L > __fmul_rn(R, 1.000004f)) { bi = inter; bd = den; }
        else if (__fmul_rn(L, 1.000004f) >= R) {
          if (__fdiv_rn(inter, den) > __fdiv_rn(bi, bd)) { bi = inter; bd = den; }
        }
      }
      unsigned v = (bi > 0.f) ? __float_as_uint(__fdiv_rn(bi, bd)) : 0u;
      unsigned mx = __reduce_max_sync(0xffffffffu, v);
      if ((t & 31) == 0 && mx) atomicMax(&smax[k], mx);
    }
  }
  __syncthreads();
  if (t < KG && smax[t]) atomicMax(&g_gtmax[b*KG + t], smax[t]);
}

__device__ __forceinline__ void emit_cand(bool pred, int b, int cat,
                                          unsigned kk0, unsigned kk1,
                                          unsigned n, unsigned m, int lane) {
  unsigned msk = __ballot_sync(0xffffffffu, pred);
  if (!msk) return;
  unsigned v = 0;
  if (pred) v = rng23(kk0, kk1, n);
  int leader = __ffs(msk) - 1;
  int base = 0;
  if (lane == leader) base = atomicAdd(&g_cnt[b*2 + cat], __popc(msk));
  base = __shfl_sync(0xffffffffu, base, leader);
  if (pred) {
    int pos = base + __popc(msk & ((1u << lane) - 1u));
    g_cand[(b*2 + cat)*NN + pos] = make_int2((int)((n << 16) | m), (int)v);
  }
}

__global__ __launch_bounds__(256) void labels_kernel(const float* __restrict__ gt,
                                                     const float* __restrict__ iminfo,
                                                     Keys keys) {
  int b = blockIdx.y, t = threadIdx.x;
  int m0 = (blockIdx.x * 256 + t) * 4;
  __shared__ float4 sbox[KG];
  __shared__ float sarea[KG];
  __shared__ float sgm[KG], slo[KG], shi[KG];
  if (t < KG) {
    const float* g = gt + (b*KG + t)*5;
    float x1 = g[0], y1 = g[1], x2 = g[2], y2 = g[3];
    sbox[t] = make_float4(x1, y1, x2, y2);
    sarea[t] = __fmul_rn(__fadd_rn(__fsub_rn(x2, x1), 1.f),
                         __fadd_rn(__fsub_rn(y2, y1), 1.f));
    float f = __uint_as_float(g_gtmax[b*KG + t]);
    f = (f == 0.f) ? 1e-5f : f;
    sgm[t] = f;
    slo[t] = __fmul_rn(f, 0.999996f);
    shi[t] = __fmul_rn(f, 1.000004f);
  }
  __syncthreads();
  float imh = iminfo[0], imw = iminfo[1];
  int a = m0 >> 12;
  int s0 = m0 & 4095;
  float c0 = c_anch[a][0], c1 = c_anch[a][1], c2 = c_anch[a][2], c3 = c_anch[a][3];
  float ax1[4], ay1[4], ax2[4], ay2[4], aarea[4];
  bool ins[4]; bool any = false;
  float bi[4], bd[4]; int barg[4]; bool isb[4];
#pragma unroll
  for (int j = 0; j < 4; j++) {
    int s = s0 + j;
    float fx = (float)((s & 63) * 16);
    float fy = (float)((s >> 6) * 16);
    ax1[j] = __fadd_rn(c0, fx); ay1[j] = __fadd_rn(c1, fy);
    ax2[j] = __fadd_rn(c2, fx); ay2[j] = __fadd_rn(c3, fy);
    aarea[j] = __fmul_rn(__fadd_rn(__fsub_rn(ax2[j], ax1[j]), 1.f),
                         __fadd_rn(__fsub_rn(ay2[j], ay1[j]), 1.f));
    ins[j] = (ax1[j] >= 0.f) && (ay1[j] >= 0.f) && (ax2[j] < imw) && (ay2[j] < imh);
    any |= ins[j];
    bi[j] = 0.f; bd[j] = 1.f; barg[j] = 0; isb[j] = false;
  }
  {
    int wrow = ((m0 & ~127) & 4095) >> 6;
    float wy1 = c1 + (float)(wrow * 16);
    float wy2 = c3 + (float)((wrow + 1) * 16);
    for (int k = 0; k < KG; k++) {
      float4 gb = sbox[k];
      // +1-inclusive IoU extent band (argmax needs even tiny overlaps)
      if (gb.y - wy2 >= 1.f || wy1 - gb.w >= 1.f) continue;
      float ga = sarea[k];
      float lo = slo[k], hi = shi[k], sv = sgm[k];
#pragma unroll
      for (int j = 0; j < 4; j++) {
        float ix = fmaxf(0.f, __fadd_rn(__fsub_rn(fminf(ax2[j], gb.z), fmaxf(ax1[j], gb.x)), 1.f));
        float iy = fmaxf(0.f, __fadd_rn(__fsub_rn(fminf(ay2[j], gb.w), fmaxf(ay1[j], gb.y)), 1.f));
        float inter = __fmul_rn(ix, iy);
        if (inter <= 0.f) continue;
        float den = __fsub_rn(__fadd_rn(aarea[j], ga), inter);
        // is_best pre-screen window, exact confirm
        if (inter >= __fmul_rn(lo, den) && inter <= __fmul_rn(hi, den))
          isb[j] |= (__fdiv_rn(inter, den) == sv);
        // float-argmax via fraction compare + exact fallback in ambiguity window
        float L = __fmul_rn(inter, bd[j]), R = __fmul_rn(bi[j], den);
        if (L > __fmul_rn(R, 1.000004f)) { bi[j] = inter; bd[j] = den; barg[j] = k; }
        else if (__fmul_rn(L, 1.000004f) >= R) {
          if (__fdiv_rn(inter, den) > __fdiv_rn(bi[j], bd[j])) {
            bi[j] = inter; bd[j] = den; barg[j] = k;
          }
        }
      }
    }
  }
  float lblv[4];
#pragma unroll
  for (int j = 0; j < 4; j++) {
    float vb = (bi[j] > 0.f) ? __fdiv_rn(bi[j], bd[j]) : 0.f;
    float l = -1.f;
    if (ins[j]) {
      if (vb < 0.3f)  l = 0.f;
      if (isb[j])     l = 1.f;
      if (vb >= 0.7f) l = 1.f;
    }
    lblv[j] = l;
  }
  *reinterpret_cast<float4*>(g_lbl + b*NN + m0) =
      make_float4(lblv[0], lblv[1], lblv[2], lblv[3]);
  uchar4 au = make_uchar4((unsigned char)barg[0], (unsigned char)barg[1],
                          (unsigned char)barg[2], (unsigned char)barg[3]);
  *reinterpret_cast<uchar4*>(g_arg + b*NN + m0) = au;
  int lane = t & 31;
  unsigned kf0 = keys.k[b][0], kf1 = keys.k[b][1];
  unsigned kb0 = keys.k[b][2], kb1 = keys.k[b][3];
#pragma unroll
  for (int j = 0; j < 4; j++) {
    unsigned s = (unsigned)(s0 + j);
    unsigned n = s * AA + (unsigned)a;
    unsigned m = (unsigned)(m0 + j);
    emit_cand(lblv[j] == 1.f, b, 0, kf0, kf1, n, m, lane);
    emit_cand(lblv[j] == 0.f, b, 1, kb0, kb1, n, m, lane);
  }
}

// keep top `limit` candidates by (rng desc, n asc); disable rest
__device__ void select_top(float* __restrict__ lbl, const int2* __restrict__ list,
                           int cnt, int limit,
                           int* hist, unsigned* tie_v, unsigned* tie_p,
                           int* wsum, int* s_sel, int t) {
#pragma unroll
  for (int i = t; i < 4096; i += NT) hist[i] = 0;
  if (t == 0) s_sel[2] = 0;
  __syncthreads();
  for (int i = t; i < cnt; i += NT) {
    unsigned v = (unsigned)list[i].y;
    atomicAdd(&hist[v >> 11], 1);
  }
  __syncthreads();
  int base = 4095 - 4*t;
  int h0 = hist[base], h1 = hist[base-1], h2 = hist[base-2], h3 = hist[base-3];
  int local = h0 + h1 + h2 + h3;
  int lane = t & 31, wid = t >> 5;
  int x = local;
#pragma unroll
  for (int o = 1; o < 32; o <<= 1) {
    int y = __shfl_up_sync(0xffffffffu, x, o);
    if (lane >= o) x += y;
  }
  if (lane == 31) wsum[wid] = x;
  __syncthreads();
  if (wid == 0) {
    int s = wsum[lane];
#pragma unroll
    for (int o = 1; o < 32; o <<= 1) {
      int y = __shfl_up_sync(0xffffffffu, s, o);
      if (lane >= o) s += y;
    }
    wsum[lane] = s;
  }
  __syncthreads();
  int prefix = (wid ? wsum[wid-1] : 0) + (x - local);
  if (prefix < limit && prefix + local >= limit) {
    int p = prefix; int hh[4] = {h0, h1, h2, h3};
#pragma unroll
    for (int j = 0; j < 4; j++) {
      if (p + hh[j] >= limit) { s_sel[0] = base - j; s_sel[1] = limit - p; break; }
      p += hh[j];
    }
  }
  __syncthreads();
  int cb = s_sel[0], r = s_sel[1];
  for (int i = t; i < cnt; i += NT) {
    int2 e = list[i];
    unsigned v = (unsigned)e.y;
    unsigned pk = (unsigned)e.x;
    int bkt = (int)(v >> 11);
    if (bkt < cb) lbl[pk & 0xFFFFu] = -1.f;
    else if (bkt == cb) {
      int p = atomicAdd(&s_sel[2], 1);
      if (p < 1024) { tie_v[p] = v; tie_p[p] = pk; }
      else lbl[pk & 0xFFFFu] = -1.f;   // statistically unreachable
    }
  }
  __syncthreads();
  int mm = min(s_sel[2], 1024);
  for (int i = t; i < mm; i += NT) {
    unsigned vi = tie_v[i]; unsigned ni = tie_p[i] >> 16; int rank = 0;
    for (int j = 0; j < mm; j++) {
      unsigned vj = tie_v[j];
      if (vj > vi || (vj == vi && (tie_p[j] >> 16) < ni)) rank++;
    }
    if (rank >= r) lbl[tie_p[i] & 0xFFFFu] = -1.f;
  }
  __syncthreads();
}

__global__ __launch_bounds__(NT) void subsample_kernel() {
  int b = blockIdx.x; int t = threadIdx.x;
  __shared__ int hist[4096];
  __shared__ unsigned tie_v[1024];
  __shared__ unsigned tie_p[1024];
  __shared__ int wsum[32];
  __shared__ int s_sel[3];
  float* lbl = g_lbl + b*NN;
  int fgc = g_cnt[b*2], bgc = g_cnt[b*2 + 1];
  if (fgc > 128)
    select_top(lbl, g_cand + (b*2)*NN, fgc, 128, hist, tie_v, tie_p, wsum, s_sel, t);
  int fg_kept = min(fgc, 128);
  int limit = 256 - fg_kept;
  if (bgc > limit)
    select_top(lbl, g_cand + (b*2 + 1)*NN, bgc, limit, hist, tie_v, tie_p, wsum, s_sel, t);
  if (t == 0) g_uw[b] = 1.f / (float)(fg_kept + min(bgc, limit));
}

__global__ void output_kernel(const float* __restrict__ gt,
                              const float* __restrict__ iminfo,
                              float* __restrict__ out) {
  int idx = blockIdx.x * 256 + threadIdx.x;      // exactly LBL_SZ threads
  int s = idx & (HWV - 1);
  int t12 = idx >> 12;
  int a = t12 % AA;
  int b = t12 / AA;
  float imh = iminfo[0], imw = iminfo[1];
  float fx = (float)((s & 63) * 16);
  float fy = (float)((s >> 6) * 16);
  float ax1 = c_anch[a][0] + fx, ay1 = c_anch[a][1] + fy;
  float ax2 = c_anch[a][2] + fx, ay2 = c_anch[a][3] + fy;
  bool inside = (ax1 >= 0.f) && (ay1 >= 0.f) && (ax2 < imw) && (ay2 < imh);
  float lbl = g_lbl[idx];                        // m-layout == output labels layout
  int arg = (int)g_arg[idx];
  const float* g = gt + (b*KG + arg)*5;
  float aw = ax2 - ax1 + 1.f, ah = ay2 - ay1 + 1.f;
  float acx = ax1 + 0.5f*(aw - 1.f), acy = ay1 + 0.5f*(ah - 1.f);
  float gw = g[2] - g[0] + 1.f, gh = g[3] - g[1] + 1.f;
  float gcx = g[0] + 0.5f*(gw - 1.f), gcy = g[1] + 0.5f*(gh - 1.f);
  float t0 = (gcx - acx) / aw;
  float t1 = (gcy - acy) / ah;
  float t2 = logf(gw / aw);
  float t3 = logf(gh / ah);
  float inw = (lbl == 1.f) ? 1.f : 0.f;
  float ow  = (lbl == 1.f || lbl == 0.f) ? g_uw[b] : 0.f;
  if (!inside) { t0 = t1 = t2 = t3 = 0.f; inw = 0.f; ow = 0.f; lbl = 0.f; }
  out[idx] = lbl;
  int cb = (b*36 + a*4)*HWV + s;
  float tv[4] = {t0, t1, t2, t3};
#pragma unroll
  for (int c4 = 0; c4 < 4; c4++) {
    out[LBL_SZ            + cb + c4*HWV] = tv[c4];
    out[LBL_SZ +   CH_SZ  + cb + c4*HWV] = inw;
    out[LBL_SZ + 2*CH_SZ  + cb + c4*HWV] = ow;
  }
}

// ---------------- host --------------------------------------------------------
extern "C" void kernel_launch(void* const* d_in, const int* in_sizes, int n_in,
                              void* d_out, int out_size) {
  const float* gt     = (const float*)d_in[1];   // (B,50,5)
  const float* iminfo = (const float*)d_in[2];   // (B,2), ref uses row 0
  float* out = (float*)d_out;

  Keys keys;
  for (int b = 0; b < BB; b++) {
#if JAX_PARTITIONABLE
    unsigned b0, b1; tf2x32(0u, 42u, 0u, (unsigned)b, b0, b1);
    unsigned f0, f1, g0, g1;
    tf2x32(b0, b1, 0u, 0u, f0, f1);
    tf2x32(b0, b1, 0u, 1u, g0, g1);
    keys.k[b][0] = f0; keys.k[b][1] = f1; keys.k[b][2] = g0; keys.k[b][3] = g1;
#else
    unsigned y0[16], y1[16], flat[32];
    for (int i = 0; i < 16; i++) tf2x32(0u, 42u, (unsigned)i, (unsigned)(i+16), y0[i], y1[i]);
    for (int i = 0; i < 16; i++) { flat[i] = y0[i]; flat[16+i] = y1[i]; }
    unsigned kb0 = flat[2*b], kb1 = flat[2*b+1];
    unsigned p00, p01, p10, p11;
    tf2x32(kb0, kb1, 0u, 2u, p00, p01);
    tf2x32(kb0, kb1, 1u, 3u, p10, p11);
    keys.k[b][0] = p00; keys.k[b][1] = p10;
    keys.k[b][2] = p01; keys.k[b][3] = p11;
#endif
  }

  zero_kernel<<<4, 256>>>();
  dim3 gA(36, BB);
  stats_kernel<<<gA, 256>>>(gt, iminfo);
  labels_kernel<<<gA, 256>>>(gt, iminfo, keys);
  subsample_kernel<<<BB, NT>>>();
  output_kernel<<<LBL_SZ/256, 256>>>(gt, iminfo, out);
}